// round 11
// baseline (speedup 1.0000x reference)
#include <cuda_runtime.h>

// CormorantCGProduct: full CG tensor product for LMAX=3, N=1024, TAU=16.
// Input order (dict insertion order): A0,B0,A1,B1,A2,B2,A3,B3,
// each (2, N, 2l+1, 16) fp32.
// Output: concat over l=0..3 of (2, N, 2l+1, 256*npairs_l) fp32.

#define NTASKS 34
#define CGSTRIDE 343

typedef unsigned long long ull;

__device__ float g_cg[NTASKS * CGSTRIDE];

// Heavy-first ordering: lo=3 (10), lo=2 (11), lo=1 (9), lo=0 (4).
__constant__ signed char c_l1[NTASKS] = {
    0,1,1,2,2,2,3,3,3,3,
    0,1,1,1,2,2,2,2,3,3,3,
    0,1,1,1,2,2,2,3,3,
    0,1,2,3};
__constant__ signed char c_l2[NTASKS] = {
    3,2,3,1,2,3,0,1,2,3,
    2,1,2,3,0,1,2,3,1,2,3,
    1,0,1,2,1,2,3,2,3,
    0,1,2,3};
__constant__ signed char c_lo[NTASKS] = {
    3,3,3,3,3,3,3,3,3,3,
    2,2,2,2,2,2,2,2,2,2,2,
    1,1,1,1,1,1,1,1,1,
    0,0,0,0};
__constant__ short c_poff[NTASKS] = {
    0,256,512,768,1024,1280,1536,1792,2048,2304,
    0,256,512,768,1024,1280,1536,1792,2048,2304,2560,
    0,256,512,768,1024,1280,1536,1792,2048,
    0,256,512,768};

__device__ __forceinline__ double dfact(int n) {
    const double f[11] = {1.,1.,2.,6.,24.,120.,720.,5040.,40320.,362880.,3628800.};
    return f[n];
}

// ---------------------------------------------------------------------------
// CG coefficient init (Condon-Shortley), exact match to reference formula.
// ---------------------------------------------------------------------------
__global__ void cg_init_kernel() {
    int t   = blockIdx.x;
    int idx = threadIdx.x;
    if (idx >= CGSTRIDE) return;

    int l1 = c_l1[t], l2 = c_l2[t], l = c_lo[t];
    int x = idx / 49;
    int y = (idx / 7) % 7;
    int z = idx % 7;

    float val = 0.0f;
    if (x <= 2 * l1 && y <= 2 * l2 && z <= 2 * l) {
        int m1 = x - l1, m2 = y - l2, m = z - l;
        if (m1 + m2 == m) {
            double pref = (2.0 * l + 1.0)
                * dfact(l + l1 - l2) * dfact(l - l1 + l2) * dfact(l1 + l2 - l)
                / dfact(l1 + l2 + l + 1)
                * dfact(l + m) * dfact(l - m)
                * dfact(l1 - m1) * dfact(l1 + m1)
                * dfact(l2 - m2) * dfact(l2 + m2);
            pref = sqrt(pref);
            int kmin = max(0, max(l2 - l - m1, l1 - l + m2));
            int kmax = min(l1 + l2 - l, min(l1 - m1, l2 + m2));
            double s = 0.0;
            for (int k = kmin; k <= kmax; ++k) {
                double den = dfact(k) * dfact(l1 + l2 - l - k)
                           * dfact(l1 - m1 - k) * dfact(l2 + m2 - k)
                           * dfact(l - l2 + m1 + k) * dfact(l - l1 - m2 + k);
                double term = 1.0 / den;
                if (k & 1) term = -term;
                s += term;
            }
            val = (float)(pref * s);
        }
    }
    g_cg[t * CGSTRIDE + idx] = val;
}

// ---- packed f32x2 + store helpers ---------------------------------------
__device__ __forceinline__ ull pack2(float lo, float hi) {
    ull r;
    asm("mov.b64 %0, {%1, %2};" : "=l"(r) : "f"(lo), "f"(hi));
    return r;
}
__device__ __forceinline__ void fma2(ull& d, ull a, ull b) {
    asm("fma.rn.f32x2 %0, %1, %2, %0;" : "+l"(d) : "l"(a), "l"(b));
}
__device__ __forceinline__ void stcs2(float* p, ull a, ull b) {
    asm volatile("st.global.cs.v2.u64 [%0], {%1, %2};" :: "l"(p), "l"(a), "l"(b) : "memory");
}

// ---------------------------------------------------------------------------
// Specialized per-task body. 128 threads = 4 n-rows x 32 lanes:
//   c = lane>>1 (A channel), d8 = (lane&1)*8 (8 consecutive B channels).
// A staged INTERLEAVED (ar,ai) -> one LDS.64 per term (conflict-free: c*2
// word stride = 16 distinct banks). z loop unrolled with compile-time bounds;
// x loop runtime (unroll 1) over the exact valid term range.
// ---------------------------------------------------------------------------
template<int L1, int L2, int LO>
__device__ __forceinline__ void task_body(
    const float* __restrict__ Aptr, const float* __restrict__ Bptr,
    float* __restrict__ out, int N, int n0, int poff, int t,
    float (*sA)[224], float (*sB)[2][112], float* __restrict__ sC)
{
    constexpr int D1 = 2 * L1 + 1, D2 = 2 * L2 + 1, DZ = 2 * LO + 1;
    constexpr int SHIFT = L1 + L2 - LO;     // y = z + SHIFT - x
    constexpr int CL = (LO == 0) ? 1024 : (LO == 1) ? 2304 : (LO == 2) ? 2816 : 2560;
    constexpr int PERA = D1 * 16, PERB = D2 * 16;

    const int tid = threadIdx.x;

    // ---- stage A interleaved (ar,ai), B row-major, CG slab ----
    for (int i = tid; i < 8 * PERA; i += 128) {
        int q = i / PERA, r = i - q * PERA;   // q = nn*2 + s ; r = x*16 + cc
        float v = Aptr[((long)((q & 1) * N + n0 + (q >> 1))) * PERA + r];
        sA[q >> 1][(r >> 4) * 32 + (r & 15) * 2 + (q & 1)] = v;
    }
    for (int i = tid; i < 8 * PERB; i += 128) {
        int q = i / PERB, r = i - q * PERB;
        sB[q >> 1][q & 1][r] = Bptr[((long)((q & 1) * N + n0 + (q >> 1))) * PERB + r];
    }
    for (int i = tid; i < CGSTRIDE; i += 128) sC[i] = g_cg[t * CGSTRIDE + i];
    __syncthreads();

    const int nn   = tid >> 5;
    const int lane = tid & 31;
    const int c    = lane >> 1;
    const int d8   = (lane & 1) * 8;
    const int n    = n0 + nn;

    const float* sAn = &sA[nn][c * 2];       // (ar,ai) pair at [x*32]
    const float* sBn = &sB[nn][0][d8];       // br row y at [y*16], bi at +112

    const long base = 2L * N * ((LO == 0) ? 0 : (LO == 1) ? 1024 : (LO == 2) ? 7936 : 22016);
    long offR = base + (long)n * DZ * CL + poff + c * 16 + d8;
    long offI = offR + (long)N * DZ * CL;

#pragma unroll
    for (int z = 0; z < DZ; ++z) {
        const int zs  = z + SHIFT;                       // compile-time per z
        const int xlo = (zs - (D2 - 1) > 0) ? zs - (D2 - 1) : 0;
        const int xhi = (zs < D1 - 1) ? zs : D1 - 1;
        const int zc  = 8 * z + 7 * SHIFT;               // CG idx = 42x + zc

        ull aR0 = 0, aR1 = 0, aR2 = 0, aR3 = 0;
        ull aI0 = 0, aI1 = 0, aI2 = 0, aI3 = 0;

#pragma unroll 1
        for (int x = xlo; x <= xhi; ++x) {
            const int y = zs - x;
            float Cv  = sC[x * 42 + zc];
            float2 a2 = *(const float2*)(sAn + x * 32);   // (ar, ai)
            float car = Cv * a2.x;
            float cai = Cv * a2.y;
            ull car2 = pack2(car,  car);
            ull caip = pack2(cai,  cai);
            ull cain = pack2(-cai, -cai);
            ulonglong2 br = *(const ulonglong2*)(sBn + y * 16);
            ulonglong2 bi = *(const ulonglong2*)(sBn + y * 16 + 112);
            fma2(aR0, car2, br.x);  fma2(aR0, cain, bi.x);
            fma2(aR1, car2, br.y);  fma2(aR1, cain, bi.y);
            fma2(aI0, car2, bi.x);  fma2(aI0, caip, br.x);
            fma2(aI1, car2, bi.y);  fma2(aI1, caip, br.y);
            ulonglong2 br2 = *(const ulonglong2*)(sBn + y * 16 + 4);
            ulonglong2 bi2 = *(const ulonglong2*)(sBn + y * 16 + 116);
            fma2(aR2, car2, br2.x); fma2(aR2, cain, bi2.x);
            fma2(aR3, car2, br2.y); fma2(aR3, cain, bi2.y);
            fma2(aI2, car2, bi2.x); fma2(aI2, caip, br2.x);
            fma2(aI3, car2, bi2.y); fma2(aI3, caip, br2.y);
        }
        stcs2(out + offR,     aR0, aR1);
        stcs2(out + offR + 4, aR2, aR3);
        stcs2(out + offI,     aI0, aI1);
        stcs2(out + offI + 4, aI2, aI3);
        offR += CL;
        offI += CL;
    }
}

// ---------------------------------------------------------------------------
__global__ void __launch_bounds__(128, 8)
cgprod_kernel(const float* __restrict__ A0, const float* __restrict__ A1,
              const float* __restrict__ A2, const float* __restrict__ A3,
              const float* __restrict__ B0, const float* __restrict__ B1,
              const float* __restrict__ B2, const float* __restrict__ B3,
              float* __restrict__ out, int N) {
    __shared__ __align__(16) float sA[4][224];     // interleaved (ar,ai)
    __shared__ __align__(16) float sB[4][2][112];
    __shared__ float sC[CGSTRIDE];

    const int t    = blockIdx.x;
    const int n0   = blockIdx.y * 4;
    const int poff = c_poff[t];

    const float* As[4] = {A0, A1, A2, A3};
    const float* Bs[4] = {B0, B1, B2, B3};

#define TB(T, LA, LB, LZ) \
    case T: task_body<LA, LB, LZ>(As[LA], Bs[LB], out, N, n0, poff, t, sA, sB, sC); break;

    switch (t) {
        TB( 0, 0,3,3) TB( 1, 1,2,3) TB( 2, 1,3,3) TB( 3, 2,1,3) TB( 4, 2,2,3)
        TB( 5, 2,3,3) TB( 6, 3,0,3) TB( 7, 3,1,3) TB( 8, 3,2,3) TB( 9, 3,3,3)
        TB(10, 0,2,2) TB(11, 1,1,2) TB(12, 1,2,2) TB(13, 1,3,2) TB(14, 2,0,2)
        TB(15, 2,1,2) TB(16, 2,2,2) TB(17, 2,3,2) TB(18, 3,1,2) TB(19, 3,2,2)
        TB(20, 3,3,2)
        TB(21, 0,1,1) TB(22, 1,0,1) TB(23, 1,1,1) TB(24, 1,2,1) TB(25, 2,1,1)
        TB(26, 2,2,1) TB(27, 2,3,1) TB(28, 3,2,1) TB(29, 3,3,1)
        TB(30, 0,0,0) TB(31, 1,1,0) TB(32, 2,2,0) TB(33, 3,3,0)
    }
#undef TB
}

// ---------------------------------------------------------------------------
extern "C" void kernel_launch(void* const* d_in, const int* in_sizes, int n_in,
                              void* d_out, int out_size) {
    // Dict insertion order in setup_inputs(): A0,B0,A1,B1,A2,B2,A3,B3
    const float* A0 = (const float*)d_in[0];
    const float* B0 = (const float*)d_in[1];
    const float* A1 = (const float*)d_in[2];
    const float* B1 = (const float*)d_in[3];
    const float* A2 = (const float*)d_in[4];
    const float* B2 = (const float*)d_in[5];
    const float* A3 = (const float*)d_in[6];
    const float* B3 = (const float*)d_in[7];
    float* out = (float*)d_out;

    int N = in_sizes[0] / (2 * 1 * 16);   // A0 is (2, N, 1, 16)

    cg_init_kernel<<<NTASKS, CGSTRIDE>>>();

    dim3 grid(NTASKS, N / 4);
    cgprod_kernel<<<grid, 128>>>(A0, A1, A2, A3, B0, B1, B2, B3, out, N);
}

// round 12
// speedup vs baseline: 1.1020x; 1.1020x over previous
#include <cuda_runtime.h>

// CormorantCGProduct: full CG tensor product for LMAX=3, N=1024, TAU=16.
// Input order (dict insertion order): A0,B0,A1,B1,A2,B2,A3,B3,
// each (2, N, 2l+1, 16) fp32.
// Output: concat over l=0..3 of (2, N, 2l+1, 256*npairs_l) fp32.

#define NTASKS 34
#define CGSTRIDE 343

typedef unsigned long long ull;

__device__ float g_cg[NTASKS * CGSTRIDE];

// Heavy-first ordering: lo=3 (10), lo=2 (11), lo=1 (9), lo=0 (4).
__constant__ signed char c_l1[NTASKS] = {
    0,1,1,2,2,2,3,3,3,3,
    0,1,1,1,2,2,2,2,3,3,3,
    0,1,1,1,2,2,2,3,3,
    0,1,2,3};
__constant__ signed char c_l2[NTASKS] = {
    3,2,3,1,2,3,0,1,2,3,
    2,1,2,3,0,1,2,3,1,2,3,
    1,0,1,2,1,2,3,2,3,
    0,1,2,3};
__constant__ signed char c_lo[NTASKS] = {
    3,3,3,3,3,3,3,3,3,3,
    2,2,2,2,2,2,2,2,2,2,2,
    1,1,1,1,1,1,1,1,1,
    0,0,0,0};
__constant__ short c_poff[NTASKS] = {
    0,256,512,768,1024,1280,1536,1792,2048,2304,
    0,256,512,768,1024,1280,1536,1792,2048,2304,2560,
    0,256,512,768,1024,1280,1536,1792,2048,
    0,256,512,768};

__device__ __forceinline__ double dfact(int n) {
    const double f[11] = {1.,1.,2.,6.,24.,120.,720.,5040.,40320.,362880.,3628800.};
    return f[n];
}

// ---------------------------------------------------------------------------
// CG coefficient init (Condon-Shortley), exact match to reference formula.
// ---------------------------------------------------------------------------
__global__ void cg_init_kernel() {
    int t   = blockIdx.x;
    int idx = threadIdx.x;
    if (idx >= CGSTRIDE) return;

    int l1 = c_l1[t], l2 = c_l2[t], l = c_lo[t];
    int x = idx / 49;
    int y = (idx / 7) % 7;
    int z = idx % 7;

    float val = 0.0f;
    if (x <= 2 * l1 && y <= 2 * l2 && z <= 2 * l) {
        int m1 = x - l1, m2 = y - l2, m = z - l;
        if (m1 + m2 == m) {
            double pref = (2.0 * l + 1.0)
                * dfact(l + l1 - l2) * dfact(l - l1 + l2) * dfact(l1 + l2 - l)
                / dfact(l1 + l2 + l + 1)
                * dfact(l + m) * dfact(l - m)
                * dfact(l1 - m1) * dfact(l1 + m1)
                * dfact(l2 - m2) * dfact(l2 + m2);
            pref = sqrt(pref);
            int kmin = max(0, max(l2 - l - m1, l1 - l + m2));
            int kmax = min(l1 + l2 - l, min(l1 - m1, l2 + m2));
            double s = 0.0;
            for (int k = kmin; k <= kmax; ++k) {
                double den = dfact(k) * dfact(l1 + l2 - l - k)
                           * dfact(l1 - m1 - k) * dfact(l2 + m2 - k)
                           * dfact(l - l2 + m1 + k) * dfact(l - l1 - m2 + k);
                double term = 1.0 / den;
                if (k & 1) term = -term;
                s += term;
            }
            val = (float)(pref * s);
        }
    }
    g_cg[t * CGSTRIDE + idx] = val;
}

// ---- packed f32x2 + store helpers ---------------------------------------
__device__ __forceinline__ ull pack2(float lo, float hi) {
    ull r;
    asm("mov.b64 %0, {%1, %2};" : "=l"(r) : "f"(lo), "f"(hi));
    return r;
}
__device__ __forceinline__ void fma2(ull& d, ull a, ull b) {
    asm("fma.rn.f32x2 %0, %1, %2, %0;" : "+l"(d) : "l"(a), "l"(b));
}
__device__ __forceinline__ void stcs2(float* p, ull a, ull b) {
    asm volatile("st.global.cs.v2.u64 [%0], {%1, %2};" :: "l"(p), "l"(a), "l"(b) : "memory");
}

// ---------------------------------------------------------------------------
// z-block: accumulate output rows z in [Z0, Z0+ZB) with B rows loaded ONCE
// per y (y-outer loop). Accumulators have compile-time indices -> registers.
// The x-validity branch inside the zz unroll is warp-uniform (y,z only).
// ---------------------------------------------------------------------------
template<int L1, int L2, int LO, int Z0, int ZB>
__device__ __forceinline__ void zblock(
    const float* __restrict__ sAn, const float* __restrict__ sBn,
    const float* __restrict__ sC,
    float* __restrict__ out, long offR, long offI)
{
    constexpr int D1 = 2 * L1 + 1, D2 = 2 * L2 + 1;
    constexpr int SHIFT = L1 + L2 - LO;     // x = z + SHIFT - y
    constexpr int CL = (LO == 0) ? 1024 : (LO == 1) ? 2304 : (LO == 2) ? 2816 : 2560;
    constexpr int YLO = (SHIFT + Z0 - (D1 - 1)) > 0 ? (SHIFT + Z0 - (D1 - 1)) : 0;
    constexpr int YHI = (SHIFT + Z0 + ZB - 1) < (D2 - 1) ? (SHIFT + Z0 + ZB - 1) : (D2 - 1);

    ull aR[ZB][2] = {}, aI[ZB][2] = {};

#pragma unroll 1
    for (int y = YLO; y <= YHI; ++y) {
        ulonglong2 br = *(const ulonglong2*)(sBn + y * 16);
        ulonglong2 bi = *(const ulonglong2*)(sBn + y * 16 + 112);
#pragma unroll
        for (int zz = 0; zz < ZB; ++zz) {
            const int z = Z0 + zz;
            const int x = z + SHIFT - y;            // runtime (y runtime)
            if (x >= 0 && x < D1) {                 // warp-uniform branch
                float Cv  = sC[49 * x + 7 * y + z];
                float2 a2 = *(const float2*)(sAn + x * 32);   // (ar, ai)
                float car = Cv * a2.x;
                float cai = Cv * a2.y;
                ull car2 = pack2(car,  car);
                ull caip = pack2(cai,  cai);
                ull cain = pack2(-cai, -cai);
                fma2(aR[zz][0], car2, br.x);  fma2(aR[zz][0], cain, bi.x);
                fma2(aR[zz][1], car2, br.y);  fma2(aR[zz][1], cain, bi.y);
                fma2(aI[zz][0], car2, bi.x);  fma2(aI[zz][0], caip, br.x);
                fma2(aI[zz][1], car2, bi.y);  fma2(aI[zz][1], caip, br.y);
            }
        }
    }
#pragma unroll
    for (int zz = 0; zz < ZB; ++zz) {
        stcs2(out + offR + (long)(Z0 + zz) * CL, aR[zz][0], aR[zz][1]);
        stcs2(out + offI + (long)(Z0 + zz) * CL, aI[zz][0], aI[zz][1]);
    }
}

// ---------------------------------------------------------------------------
// Specialized per-task body. 256 threads = 4 n-rows x 64 lanes (d4 mapping):
//   c = lane>>2 (A channel), d4 = (lane&3)*4 (4 consecutive B channels).
// ---------------------------------------------------------------------------
template<int L1, int L2, int LO>
__device__ __forceinline__ void task_body(
    const float* __restrict__ Aptr, const float* __restrict__ Bptr,
    float* __restrict__ out, int N, int n0, int poff, int t,
    float (*sA)[224], float (*sB)[2][112], float* __restrict__ sC)
{
    constexpr int D1 = 2 * L1 + 1, D2 = 2 * L2 + 1, DZ = 2 * LO + 1;
    constexpr int CL = (LO == 0) ? 1024 : (LO == 1) ? 2304 : (LO == 2) ? 2816 : 2560;
    constexpr int PERA = D1 * 16, PERB = D2 * 16;

    const int tid = threadIdx.x;

    // ---- stage A interleaved (ar,ai), B row-major, CG slab ----
    for (int i = tid; i < 8 * PERA; i += 256) {
        int q = i / PERA, r = i - q * PERA;   // q = nn*2 + s ; r = x*16 + cc
        float v = Aptr[((long)((q & 1) * N + n0 + (q >> 1))) * PERA + r];
        sA[q >> 1][(r >> 4) * 32 + (r & 15) * 2 + (q & 1)] = v;
    }
    for (int i = tid; i < 8 * PERB; i += 256) {
        int q = i / PERB, r = i - q * PERB;
        sB[q >> 1][q & 1][r] = Bptr[((long)((q & 1) * N + n0 + (q >> 1))) * PERB + r];
    }
    for (int i = tid; i < CGSTRIDE; i += 256) sC[i] = g_cg[t * CGSTRIDE + i];
    __syncthreads();

    const int nn   = tid >> 6;
    const int lane = tid & 63;
    const int c    = lane >> 2;
    const int d4   = (lane & 3) * 4;
    const int n    = n0 + nn;

    const float* sAn = &sA[nn][c * 2];       // (ar,ai) pair at [x*32]
    const float* sBn = &sB[nn][0][d4];       // br row y at [y*16], bi at +112

    const long base = 2L * N * ((LO == 0) ? 0 : (LO == 1) ? 1024 : (LO == 2) ? 7936 : 22016);
    long offR = base + (long)n * DZ * CL + poff + c * 16 + d4;
    long offI = offR + (long)N * DZ * CL;

    if constexpr (DZ == 1) {
        zblock<L1, L2, LO, 0, 1>(sAn, sBn, sC, out, offR, offI);
    } else if constexpr (DZ == 3) {
        zblock<L1, L2, LO, 0, 3>(sAn, sBn, sC, out, offR, offI);
    } else if constexpr (DZ == 5) {
        zblock<L1, L2, LO, 0, 3>(sAn, sBn, sC, out, offR, offI);
        zblock<L1, L2, LO, 3, 2>(sAn, sBn, sC, out, offR, offI);
    } else {
        zblock<L1, L2, LO, 0, 4>(sAn, sBn, sC, out, offR, offI);
        zblock<L1, L2, LO, 4, 3>(sAn, sBn, sC, out, offR, offI);
    }
}

// ---------------------------------------------------------------------------
__global__ void __launch_bounds__(256, 4)
cgprod_kernel(const float* __restrict__ A0, const float* __restrict__ A1,
              const float* __restrict__ A2, const float* __restrict__ A3,
              const float* __restrict__ B0, const float* __restrict__ B1,
              const float* __restrict__ B2, const float* __restrict__ B3,
              float* __restrict__ out, int N) {
    __shared__ __align__(16) float sA[4][224];     // interleaved (ar,ai)
    __shared__ __align__(16) float sB[4][2][112];
    __shared__ float sC[CGSTRIDE];

    const int t    = blockIdx.x;
    const int n0   = blockIdx.y * 4;
    const int poff = c_poff[t];

    const float* As[4] = {A0, A1, A2, A3};
    const float* Bs[4] = {B0, B1, B2, B3};

#define TB(T, LA, LB, LZ) \
    case T: task_body<LA, LB, LZ>(As[LA], Bs[LB], out, N, n0, poff, t, sA, sB, sC); break;

    switch (t) {
        TB( 0, 0,3,3) TB( 1, 1,2,3) TB( 2, 1,3,3) TB( 3, 2,1,3) TB( 4, 2,2,3)
        TB( 5, 2,3,3) TB( 6, 3,0,3) TB( 7, 3,1,3) TB( 8, 3,2,3) TB( 9, 3,3,3)
        TB(10, 0,2,2) TB(11, 1,1,2) TB(12, 1,2,2) TB(13, 1,3,2) TB(14, 2,0,2)
        TB(15, 2,1,2) TB(16, 2,2,2) TB(17, 2,3,2) TB(18, 3,1,2) TB(19, 3,2,2)
        TB(20, 3,3,2)
        TB(21, 0,1,1) TB(22, 1,0,1) TB(23, 1,1,1) TB(24, 1,2,1) TB(25, 2,1,1)
        TB(26, 2,2,1) TB(27, 2,3,1) TB(28, 3,2,1) TB(29, 3,3,1)
        TB(30, 0,0,0) TB(31, 1,1,0) TB(32, 2,2,0) TB(33, 3,3,0)
    }
#undef TB
}

// ---------------------------------------------------------------------------
extern "C" void kernel_launch(void* const* d_in, const int* in_sizes, int n_in,
                              void* d_out, int out_size) {
    // Dict insertion order in setup_inputs(): A0,B0,A1,B1,A2,B2,A3,B3
    const float* A0 = (const float*)d_in[0];
    const float* B0 = (const float*)d_in[1];
    const float* A1 = (const float*)d_in[2];
    const float* B1 = (const float*)d_in[3];
    const float* A2 = (const float*)d_in[4];
    const float* B2 = (const float*)d_in[5];
    const float* A3 = (const float*)d_in[6];
    const float* B3 = (const float*)d_in[7];
    float* out = (float*)d_out;

    int N = in_sizes[0] / (2 * 1 * 16);   // A0 is (2, N, 1, 16)

    cg_init_kernel<<<NTASKS, CGSTRIDE>>>();

    dim3 grid(NTASKS, N / 4);
    cgprod_kernel<<<grid, 256>>>(A0, A1, A2, A3, B0, B1, B2, B3, out, N);
}

// round 14
// speedup vs baseline: 1.2210x; 1.1080x over previous
#include <cuda_runtime.h>

// CormorantCGProduct: full CG tensor product for LMAX=3, N=1024, TAU=16.
// Input order (dict insertion order): A0,B0,A1,B1,A2,B2,A3,B3,
// each (2, N, 2l+1, 16) fp32.
// Output: concat over l=0..3 of (2, N, 2l+1, 256*npairs_l) fp32.

#define NTASKS 34
#define CGSTRIDE 343

typedef unsigned long long ull;

__device__ float g_cg[NTASKS * CGSTRIDE];

// Heavy-first ordering: lo=3 (10), lo=2 (11), lo=1 (9), lo=0 (4).
__constant__ signed char c_l1[NTASKS] = {
    0,1,1,2,2,2,3,3,3,3,
    0,1,1,1,2,2,2,2,3,3,3,
    0,1,1,1,2,2,2,3,3,
    0,1,2,3};
__constant__ signed char c_l2[NTASKS] = {
    3,2,3,1,2,3,0,1,2,3,
    2,1,2,3,0,1,2,3,1,2,3,
    1,0,1,2,1,2,3,2,3,
    0,1,2,3};
__constant__ signed char c_lo[NTASKS] = {
    3,3,3,3,3,3,3,3,3,3,
    2,2,2,2,2,2,2,2,2,2,2,
    1,1,1,1,1,1,1,1,1,
    0,0,0,0};
__constant__ short c_poff[NTASKS] = {
    0,256,512,768,1024,1280,1536,1792,2048,2304,
    0,256,512,768,1024,1280,1536,1792,2048,2304,2560,
    0,256,512,768,1024,1280,1536,1792,2048,
    0,256,512,768};

__device__ __forceinline__ double dfact(int n) {
    const double f[11] = {1.,1.,2.,6.,24.,120.,720.,5040.,40320.,362880.,3628800.};
    return f[n];
}

// ---------------------------------------------------------------------------
// CG coefficient init (Condon-Shortley), exact match to reference formula.
// ---------------------------------------------------------------------------
__global__ void cg_init_kernel() {
    int t   = blockIdx.x;
    int idx = threadIdx.x;
    if (idx >= CGSTRIDE) return;

    int l1 = c_l1[t], l2 = c_l2[t], l = c_lo[t];
    int x = idx / 49;
    int y = (idx / 7) % 7;
    int z = idx % 7;

    float val = 0.0f;
    if (x <= 2 * l1 && y <= 2 * l2 && z <= 2 * l) {
        int m1 = x - l1, m2 = y - l2, m = z - l;
        if (m1 + m2 == m) {
            double pref = (2.0 * l + 1.0)
                * dfact(l + l1 - l2) * dfact(l - l1 + l2) * dfact(l1 + l2 - l)
                / dfact(l1 + l2 + l + 1)
                * dfact(l + m) * dfact(l - m)
                * dfact(l1 - m1) * dfact(l1 + m1)
                * dfact(l2 - m2) * dfact(l2 + m2);
            pref = sqrt(pref);
            int kmin = max(0, max(l2 - l - m1, l1 - l + m2));
            int kmax = min(l1 + l2 - l, min(l1 - m1, l2 + m2));
            double s = 0.0;
            for (int k = kmin; k <= kmax; ++k) {
                double den = dfact(k) * dfact(l1 + l2 - l - k)
                           * dfact(l1 - m1 - k) * dfact(l2 + m2 - k)
                           * dfact(l - l2 + m1 + k) * dfact(l - l1 - m2 + k);
                double term = 1.0 / den;
                if (k & 1) term = -term;
                s += term;
            }
            val = (float)(pref * s);
        }
    }
    g_cg[t * CGSTRIDE + idx] = val;
}

// ---- packed f32x2 + store helpers ---------------------------------------
__device__ __forceinline__ ull pack2(float lo, float hi) {
    ull r;
    asm("mov.b64 %0, {%1, %2};" : "=l"(r) : "f"(lo), "f"(hi));
    return r;
}
__device__ __forceinline__ void fma2(ull& d, ull a, ull b) {
    asm("fma.rn.f32x2 %0, %1, %2, %0;" : "+l"(d) : "l"(a), "l"(b));
}
__device__ __forceinline__ void stcs2(float* p, ull a, ull b) {
    asm volatile("st.global.cs.v2.u64 [%0], {%1, %2};" :: "l"(p), "l"(a), "l"(b) : "memory");
}

// ---------------------------------------------------------------------------
// z-block: accumulate output rows z in [Z0, Z0+ZB) with B rows loaded ONCE
// per y (y-outer loop). ZB <= 2 keeps accumulators to <= 8 ull registers.
// The x-validity branch inside the zz unroll is warp-uniform (y,z only).
// ---------------------------------------------------------------------------
template<int L1, int L2, int LO, int Z0, int ZB>
__device__ __forceinline__ void zblock(
    const float* __restrict__ sAn, const float* __restrict__ sBn,
    const float* __restrict__ sC,
    float* __restrict__ out, unsigned offR, unsigned offI)
{
    constexpr int D1 = 2 * L1 + 1, D2 = 2 * L2 + 1;
    constexpr int SHIFT = L1 + L2 - LO;     // x = z + SHIFT - y
    constexpr int CL = (LO == 0) ? 1024 : (LO == 1) ? 2304 : (LO == 2) ? 2816 : 2560;
    constexpr int YLO = (SHIFT + Z0 - (D1 - 1)) > 0 ? (SHIFT + Z0 - (D1 - 1)) : 0;
    constexpr int YHI = (SHIFT + Z0 + ZB - 1) < (D2 - 1) ? (SHIFT + Z0 + ZB - 1) : (D2 - 1);

    ull aR[ZB][2] = {}, aI[ZB][2] = {};

#pragma unroll 1
    for (int y = YLO; y <= YHI; ++y) {
        ulonglong2 br = *(const ulonglong2*)(sBn + y * 16);
        ulonglong2 bi = *(const ulonglong2*)(sBn + y * 16 + 112);
#pragma unroll
        for (int zz = 0; zz < ZB; ++zz) {
            const int z = Z0 + zz;
            const int x = z + SHIFT - y;            // runtime (y runtime)
            if (x >= 0 && x < D1) {                 // warp-uniform branch
                float Cv  = sC[49 * x + 7 * y + z];
                float2 a2 = *(const float2*)(sAn + x * 32);   // (ar, ai)
                float car = Cv * a2.x;
                float cai = Cv * a2.y;
                ull car2 = pack2(car,  car);
                ull caip = pack2(cai,  cai);
                ull cain = pack2(-cai, -cai);
                fma2(aR[zz][0], car2, br.x);  fma2(aR[zz][0], cain, bi.x);
                fma2(aR[zz][1], car2, br.y);  fma2(aR[zz][1], cain, bi.y);
                fma2(aI[zz][0], car2, bi.x);  fma2(aI[zz][0], caip, br.x);
                fma2(aI[zz][1], car2, bi.y);  fma2(aI[zz][1], caip, br.y);
            }
        }
    }
#pragma unroll
    for (int zz = 0; zz < ZB; ++zz) {
        stcs2(out + offR + (Z0 + zz) * CL, aR[zz][0], aR[zz][1]);
        stcs2(out + offI + (Z0 + zz) * CL, aI[zz][0], aI[zz][1]);
    }
}

// ---------------------------------------------------------------------------
// Specialized per-task body. 256 threads = 4 n-rows x 64 lanes (d4 mapping):
//   c = lane>>2 (A channel), d4 = (lane&3)*4 (4 consecutive B channels).
// ---------------------------------------------------------------------------
template<int L1, int L2, int LO>
__device__ __forceinline__ void task_body(
    const float* __restrict__ Aptr, const float* __restrict__ Bptr,
    float* __restrict__ out, int N, int n0, int poff, int t,
    float (*sA)[224], float (*sB)[2][112], float* __restrict__ sC)
{
    constexpr int D1 = 2 * L1 + 1, D2 = 2 * L2 + 1, DZ = 2 * LO + 1;
    constexpr int CL = (LO == 0) ? 1024 : (LO == 1) ? 2304 : (LO == 2) ? 2816 : 2560;
    constexpr int PERA = D1 * 16, PERB = D2 * 16;

    const int tid = threadIdx.x;

    // ---- stage A interleaved (ar,ai), B row-major, CG slab ----
    for (int i = tid; i < 8 * PERA; i += 256) {
        int q = i / PERA, r = i - q * PERA;   // q = nn*2 + s ; r = x*16 + cc
        float v = Aptr[((long)((q & 1) * N + n0 + (q >> 1))) * PERA + r];
        sA[q >> 1][(r >> 4) * 32 + (r & 15) * 2 + (q & 1)] = v;
    }
    for (int i = tid; i < 8 * PERB; i += 256) {
        int q = i / PERB, r = i - q * PERB;
        sB[q >> 1][q & 1][r] = Bptr[((long)((q & 1) * N + n0 + (q >> 1))) * PERB + r];
    }
    for (int i = tid; i < CGSTRIDE; i += 256) sC[i] = g_cg[t * CGSTRIDE + i];
    __syncthreads();

    const int nn   = tid >> 6;
    const int lane = tid & 63;
    const int c    = lane >> 2;
    const int d4   = (lane & 3) * 4;
    const int n    = n0 + nn;

    const float* sAn = &sA[nn][c * 2];       // (ar,ai) pair at [x*32]
    const float* sBn = &sB[nn][0][d4];       // br row y at [y*16], bi at +112

    // 32-bit offsets: total output = 81,788,928 floats < 2^31.
    const unsigned base = 2u * (unsigned)N *
        ((LO == 0) ? 0u : (LO == 1) ? 1024u : (LO == 2) ? 7936u : 22016u);
    const unsigned offR = base + (unsigned)n * (DZ * CL) + poff + c * 16 + d4;
    const unsigned offI = offR + (unsigned)N * (DZ * CL);

    if constexpr (DZ == 1) {
        zblock<L1, L2, LO, 0, 1>(sAn, sBn, sC, out, offR, offI);
    } else if constexpr (DZ == 3) {
        zblock<L1, L2, LO, 0, 2>(sAn, sBn, sC, out, offR, offI);
        zblock<L1, L2, LO, 2, 1>(sAn, sBn, sC, out, offR, offI);
    } else if constexpr (DZ == 5) {
        zblock<L1, L2, LO, 0, 2>(sAn, sBn, sC, out, offR, offI);
        zblock<L1, L2, LO, 2, 2>(sAn, sBn, sC, out, offR, offI);
        zblock<L1, L2, LO, 4, 1>(sAn, sBn, sC, out, offR, offI);
    } else {
        zblock<L1, L2, LO, 0, 2>(sAn, sBn, sC, out, offR, offI);
        zblock<L1, L2, LO, 2, 2>(sAn, sBn, sC, out, offR, offI);
        zblock<L1, L2, LO, 4, 2>(sAn, sBn, sC, out, offR, offI);
        zblock<L1, L2, LO, 6, 1>(sAn, sBn, sC, out, offR, offI);
    }
}

// ---------------------------------------------------------------------------
__global__ void __launch_bounds__(256, 5)
cgprod_kernel(const float* __restrict__ A0, const float* __restrict__ A1,
              const float* __restrict__ A2, const float* __restrict__ A3,
              const float* __restrict__ B0, const float* __restrict__ B1,
              const float* __restrict__ B2, const float* __restrict__ B3,
              float* __restrict__ out, int N) {
    __shared__ __align__(16) float sA[4][224];     // interleaved (ar,ai)
    __shared__ __align__(16) float sB[4][2][112];
    __shared__ float sC[CGSTRIDE];

    const int t    = blockIdx.x;
    const int n0   = blockIdx.y * 4;
    const int poff = c_poff[t];

    const float* As[4] = {A0, A1, A2, A3};
    const float* Bs[4] = {B0, B1, B2, B3};

#define TB(T, LA, LB, LZ) \
    case T: task_body<LA, LB, LZ>(As[LA], Bs[LB], out, N, n0, poff, t, sA, sB, sC); break;

    switch (t) {
        TB( 0, 0,3,3) TB( 1, 1,2,3) TB( 2, 1,3,3) TB( 3, 2,1,3) TB( 4, 2,2,3)
        TB( 5, 2,3,3) TB( 6, 3,0,3) TB( 7, 3,1,3) TB( 8, 3,2,3) TB( 9, 3,3,3)
        TB(10, 0,2,2) TB(11, 1,1,2) TB(12, 1,2,2) TB(13, 1,3,2) TB(14, 2,0,2)
        TB(15, 2,1,2) TB(16, 2,2,2) TB(17, 2,3,2) TB(18, 3,1,2) TB(19, 3,2,2)
        TB(20, 3,3,2)
        TB(21, 0,1,1) TB(22, 1,0,1) TB(23, 1,1,1) TB(24, 1,2,1) TB(25, 2,1,1)
        TB(26, 2,2,1) TB(27, 2,3,1) TB(28, 3,2,1) TB(29, 3,3,1)
        TB(30, 0,0,0) TB(31, 1,1,0) TB(32, 2,2,0) TB(33, 3,3,0)
    }
#undef TB
}

// ---------------------------------------------------------------------------
extern "C" void kernel_launch(void* const* d_in, const int* in_sizes, int n_in,
                              void* d_out, int out_size) {
    // Dict insertion order in setup_inputs(): A0,B0,A1,B1,A2,B2,A3,B3
    const float* A0 = (const float*)d_in[0];
    const float* B0 = (const float*)d_in[1];
    const float* A1 = (const float*)d_in[2];
    const float* B1 = (const float*)d_in[3];
    const float* A2 = (const float*)d_in[4];
    const float* B2 = (const float*)d_in[5];
    const float* A3 = (const float*)d_in[6];
    const float* B3 = (const float*)d_in[7];
    float* out = (float*)d_out;

    int N = in_sizes[0] / (2 * 1 * 16);   // A0 is (2, N, 1, 16)

    cg_init_kernel<<<NTASKS, CGSTRIDE>>>();

    dim3 grid(NTASKS, N / 4);
    cgprod_kernel<<<grid, 256>>>(A0, A1, A2, A3, B0, B1, B2, B3, out, N);
}

// round 15
// speedup vs baseline: 1.2436x; 1.0185x over previous
#include <cuda_runtime.h>

// CormorantCGProduct: full CG tensor product for LMAX=3, N=1024, TAU=16.
// Input order (dict insertion order): A0,B0,A1,B1,A2,B2,A3,B3,
// each (2, N, 2l+1, 16) fp32.
// Output: concat over l=0..3 of (2, N, 2l+1, 256*npairs_l) fp32.

#define NTASKS 34
#define CGSTRIDE 343

typedef unsigned long long ull;

__device__ float g_cg[NTASKS * CGSTRIDE];

// Heavy-first ordering: lo=3 (10), lo=2 (11), lo=1 (9), lo=0 (4).
__constant__ signed char c_l1[NTASKS] = {
    0,1,1,2,2,2,3,3,3,3,
    0,1,1,1,2,2,2,2,3,3,3,
    0,1,1,1,2,2,2,3,3,
    0,1,2,3};
__constant__ signed char c_l2[NTASKS] = {
    3,2,3,1,2,3,0,1,2,3,
    2,1,2,3,0,1,2,3,1,2,3,
    1,0,1,2,1,2,3,2,3,
    0,1,2,3};
__constant__ signed char c_lo[NTASKS] = {
    3,3,3,3,3,3,3,3,3,3,
    2,2,2,2,2,2,2,2,2,2,2,
    1,1,1,1,1,1,1,1,1,
    0,0,0,0};
__constant__ short c_poff[NTASKS] = {
    0,256,512,768,1024,1280,1536,1792,2048,2304,
    0,256,512,768,1024,1280,1536,1792,2048,2304,2560,
    0,256,512,768,1024,1280,1536,1792,2048,
    0,256,512,768};

__device__ __forceinline__ double dfact(int n) {
    const double f[11] = {1.,1.,2.,6.,24.,120.,720.,5040.,40320.,362880.,3628800.};
    return f[n];
}

// ---------------------------------------------------------------------------
// CG coefficient init (Condon-Shortley), exact match to reference formula.
// ---------------------------------------------------------------------------
__global__ void cg_init_kernel() {
    int t   = blockIdx.x;
    int idx = threadIdx.x;
    if (idx >= CGSTRIDE) return;

    int l1 = c_l1[t], l2 = c_l2[t], l = c_lo[t];
    int x = idx / 49;
    int y = (idx / 7) % 7;
    int z = idx % 7;

    float val = 0.0f;
    if (x <= 2 * l1 && y <= 2 * l2 && z <= 2 * l) {
        int m1 = x - l1, m2 = y - l2, m = z - l;
        if (m1 + m2 == m) {
            double pref = (2.0 * l + 1.0)
                * dfact(l + l1 - l2) * dfact(l - l1 + l2) * dfact(l1 + l2 - l)
                / dfact(l1 + l2 + l + 1)
                * dfact(l + m) * dfact(l - m)
                * dfact(l1 - m1) * dfact(l1 + m1)
                * dfact(l2 - m2) * dfact(l2 + m2);
            pref = sqrt(pref);
            int kmin = max(0, max(l2 - l - m1, l1 - l + m2));
            int kmax = min(l1 + l2 - l, min(l1 - m1, l2 + m2));
            double s = 0.0;
            for (int k = kmin; k <= kmax; ++k) {
                double den = dfact(k) * dfact(l1 + l2 - l - k)
                           * dfact(l1 - m1 - k) * dfact(l2 + m2 - k)
                           * dfact(l - l2 + m1 + k) * dfact(l - l1 - m2 + k);
                double term = 1.0 / den;
                if (k & 1) term = -term;
                s += term;
            }
            val = (float)(pref * s);
        }
    }
    g_cg[t * CGSTRIDE + idx] = val;
}

// ---- packed f32x2 + store helpers ---------------------------------------
__device__ __forceinline__ ull pack2(float lo, float hi) {
    ull r;
    asm("mov.b64 %0, {%1, %2};" : "=l"(r) : "f"(lo), "f"(hi));
    return r;
}
__device__ __forceinline__ void fma2(ull& d, ull a, ull b) {
    asm("fma.rn.f32x2 %0, %1, %2, %0;" : "+l"(d) : "l"(a), "l"(b));
}
__device__ __forceinline__ void stcs2(float* p, ull a, ull b) {
    asm volatile("st.global.cs.v2.u64 [%0], {%1, %2};" :: "l"(p), "l"(a), "l"(b) : "memory");
}

// ---------------------------------------------------------------------------
// z-block: accumulate output rows z in [Z0, Z0+ZB) with B rows loaded ONCE
// per y (y-outer loop). ZB <= 2 keeps accumulators to <= 8 ull registers.
// The x-validity branch inside the zz unroll is warp-uniform (y,z only).
// ---------------------------------------------------------------------------
template<int L1, int L2, int LO, int Z0, int ZB>
__device__ __forceinline__ void zblock(
    const float* __restrict__ sAn, const float* __restrict__ sBn,
    const float* __restrict__ sC,
    float* __restrict__ out, unsigned offR, unsigned offI)
{
    constexpr int D1 = 2 * L1 + 1, D2 = 2 * L2 + 1;
    constexpr int SHIFT = L1 + L2 - LO;     // x = z + SHIFT - y
    constexpr int CL = (LO == 0) ? 1024 : (LO == 1) ? 2304 : (LO == 2) ? 2816 : 2560;
    constexpr int YLO = (SHIFT + Z0 - (D1 - 1)) > 0 ? (SHIFT + Z0 - (D1 - 1)) : 0;
    constexpr int YHI = (SHIFT + Z0 + ZB - 1) < (D2 - 1) ? (SHIFT + Z0 + ZB - 1) : (D2 - 1);

    ull aR[ZB][2] = {}, aI[ZB][2] = {};

#pragma unroll 1
    for (int y = YLO; y <= YHI; ++y) {
        ulonglong2 br = *(const ulonglong2*)(sBn + y * 16);
        ulonglong2 bi = *(const ulonglong2*)(sBn + y * 16 + 112);
#pragma unroll
        for (int zz = 0; zz < ZB; ++zz) {
            const int z = Z0 + zz;
            const int x = z + SHIFT - y;            // runtime (y runtime)
            if (x >= 0 && x < D1) {                 // warp-uniform branch
                float Cv  = sC[49 * x + 7 * y + z];
                float2 a2 = *(const float2*)(sAn + x * 32);   // (ar, ai)
                float car = Cv * a2.x;
                float cai = Cv * a2.y;
                ull car2 = pack2(car,  car);
                ull caip = pack2(cai,  cai);
                ull cain = pack2(-cai, -cai);
                fma2(aR[zz][0], car2, br.x);  fma2(aR[zz][0], cain, bi.x);
                fma2(aR[zz][1], car2, br.y);  fma2(aR[zz][1], cain, bi.y);
                fma2(aI[zz][0], car2, bi.x);  fma2(aI[zz][0], caip, br.x);
                fma2(aI[zz][1], car2, bi.y);  fma2(aI[zz][1], caip, br.y);
            }
        }
    }
#pragma unroll
    for (int zz = 0; zz < ZB; ++zz) {
        stcs2(out + offR + (Z0 + zz) * CL, aR[zz][0], aR[zz][1]);
        stcs2(out + offI + (Z0 + zz) * CL, aI[zz][0], aI[zz][1]);
    }
}

// ---------------------------------------------------------------------------
// Specialized per-task body. 256 threads = 4 n-rows x 64 lanes (d4 mapping):
//   c = lane>>2 (A channel), d4 = (lane&3)*4 (4 consecutive B channels).
// ---------------------------------------------------------------------------
template<int L1, int L2, int LO>
__device__ __forceinline__ void task_body(
    const float* __restrict__ Aptr, const float* __restrict__ Bptr,
    float* __restrict__ out, int N, int n0, int poff, int t,
    float (*sA)[224], float (*sB)[2][112], float* __restrict__ sC)
{
    constexpr int D1 = 2 * L1 + 1, D2 = 2 * L2 + 1, DZ = 2 * LO + 1;
    constexpr int CL = (LO == 0) ? 1024 : (LO == 1) ? 2304 : (LO == 2) ? 2816 : 2560;
    constexpr int PERA = D1 * 16, PERB = D2 * 16;

    const int tid = threadIdx.x;

    // ---- stage A interleaved (ar,ai), B row-major, CG slab ----
    for (int i = tid; i < 8 * PERA; i += 256) {
        int q = i / PERA, r = i - q * PERA;   // q = nn*2 + s ; r = x*16 + cc
        float v = Aptr[((long)((q & 1) * N + n0 + (q >> 1))) * PERA + r];
        sA[q >> 1][(r >> 4) * 32 + (r & 15) * 2 + (q & 1)] = v;
    }
    for (int i = tid; i < 8 * PERB; i += 256) {
        int q = i / PERB, r = i - q * PERB;
        sB[q >> 1][q & 1][r] = Bptr[((long)((q & 1) * N + n0 + (q >> 1))) * PERB + r];
    }
    for (int i = tid; i < CGSTRIDE; i += 256) sC[i] = g_cg[t * CGSTRIDE + i];
    __syncthreads();

    const int nn   = tid >> 6;
    const int lane = tid & 63;
    const int c    = lane >> 2;
    const int d4   = (lane & 3) * 4;
    const int n    = n0 + nn;

    const float* sAn = &sA[nn][c * 2];       // (ar,ai) pair at [x*32]
    const float* sBn = &sB[nn][0][d4];       // br row y at [y*16], bi at +112

    // 32-bit offsets: total output = 81,788,928 floats < 2^31.
    const unsigned base = 2u * (unsigned)N *
        ((LO == 0) ? 0u : (LO == 1) ? 1024u : (LO == 2) ? 7936u : 22016u);
    const unsigned offR = base + (unsigned)n * (DZ * CL) + poff + c * 16 + d4;
    const unsigned offI = offR + (unsigned)N * (DZ * CL);

    if constexpr (DZ == 1) {
        zblock<L1, L2, LO, 0, 1>(sAn, sBn, sC, out, offR, offI);
    } else if constexpr (DZ == 3) {
        zblock<L1, L2, LO, 0, 2>(sAn, sBn, sC, out, offR, offI);
        zblock<L1, L2, LO, 2, 1>(sAn, sBn, sC, out, offR, offI);
    } else if constexpr (DZ == 5) {
        zblock<L1, L2, LO, 0, 2>(sAn, sBn, sC, out, offR, offI);
        zblock<L1, L2, LO, 2, 2>(sAn, sBn, sC, out, offR, offI);
        zblock<L1, L2, LO, 4, 1>(sAn, sBn, sC, out, offR, offI);
    } else {
        zblock<L1, L2, LO, 0, 2>(sAn, sBn, sC, out, offR, offI);
        zblock<L1, L2, LO, 2, 2>(sAn, sBn, sC, out, offR, offI);
        zblock<L1, L2, LO, 4, 2>(sAn, sBn, sC, out, offR, offI);
        zblock<L1, L2, LO, 6, 1>(sAn, sBn, sC, out, offR, offI);
    }
}

// ---------------------------------------------------------------------------
__global__ void __launch_bounds__(256, 6)
cgprod_kernel(const float* __restrict__ A0, const float* __restrict__ A1,
              const float* __restrict__ A2, const float* __restrict__ A3,
              const float* __restrict__ B0, const float* __restrict__ B1,
              const float* __restrict__ B2, const float* __restrict__ B3,
              float* __restrict__ out, int N) {
    __shared__ __align__(16) float sA[4][224];     // interleaved (ar,ai)
    __shared__ __align__(16) float sB[4][2][112];
    __shared__ float sC[CGSTRIDE];

    const int t    = blockIdx.x;
    const int n0   = blockIdx.y * 4;
    const int poff = c_poff[t];

    const float* As[4] = {A0, A1, A2, A3};
    const float* Bs[4] = {B0, B1, B2, B3};

#define TB(T, LA, LB, LZ) \
    case T: task_body<LA, LB, LZ>(As[LA], Bs[LB], out, N, n0, poff, t, sA, sB, sC); break;

    switch (t) {
        TB( 0, 0,3,3) TB( 1, 1,2,3) TB( 2, 1,3,3) TB( 3, 2,1,3) TB( 4, 2,2,3)
        TB( 5, 2,3,3) TB( 6, 3,0,3) TB( 7, 3,1,3) TB( 8, 3,2,3) TB( 9, 3,3,3)
        TB(10, 0,2,2) TB(11, 1,1,2) TB(12, 1,2,2) TB(13, 1,3,2) TB(14, 2,0,2)
        TB(15, 2,1,2) TB(16, 2,2,2) TB(17, 2,3,2) TB(18, 3,1,2) TB(19, 3,2,2)
        TB(20, 3,3,2)
        TB(21, 0,1,1) TB(22, 1,0,1) TB(23, 1,1,1) TB(24, 1,2,1) TB(25, 2,1,1)
        TB(26, 2,2,1) TB(27, 2,3,1) TB(28, 3,2,1) TB(29, 3,3,1)
        TB(30, 0,0,0) TB(31, 1,1,0) TB(32, 2,2,0) TB(33, 3,3,0)
    }
#undef TB
}

// ---------------------------------------------------------------------------
extern "C" void kernel_launch(void* const* d_in, const int* in_sizes, int n_in,
                              void* d_out, int out_size) {
    // Dict insertion order in setup_inputs(): A0,B0,A1,B1,A2,B2,A3,B3
    const float* A0 = (const float*)d_in[0];
    const float* B0 = (const float*)d_in[1];
    const float* A1 = (const float*)d_in[2];
    const float* B1 = (const float*)d_in[3];
    const float* A2 = (const float*)d_in[4];
    const float* B2 = (const float*)d_in[5];
    const float* A3 = (const float*)d_in[6];
    const float* B3 = (const float*)d_in[7];
    float* out = (float*)d_out;

    int N = in_sizes[0] / (2 * 1 * 16);   // A0 is (2, N, 1, 16)

    cg_init_kernel<<<NTASKS, CGSTRIDE>>>();

    dim3 grid(NTASKS, N / 4);
    cgprod_kernel<<<grid, 256>>>(A0, A1, A2, A3, B0, B1, B2, B3, out, N);
}